// round 6
// baseline (speedup 1.0000x reference)
#include <cuda_runtime.h>
#include <cuda_bf16.h>

// SymmetryAwareLossLoop: mean over B of min over (C,S) geodesic angle between
// R_pred[b,c] and R_s @ R_gt[b], for the 12 proper rotations of P622.
//
// tr(R_pred (R_s R_gt)^T) = <R_s, P>, P = R_pred R_gt^T; P622 traces collapse
// to closed form (+/- pairs); acos monotone -> min theta = acos(clip(max tr)).
//
// R6: thread = quad of 4 consecutive candidates (144B = 9 aligned float4).
// Warp loads are fully coalesced LDG.128 (no L1tex replay tax, which bound R4
// at ~10.5us). MLP=9 per thread, no smem staging, no load->compute barrier.
// Fix vs R5: xor-offsets {8,16} sum each 8-lane group exactly once -> no 1/8
// rescale (R5's *0.125f caused rel_err = 0.875).

#define B_TOTAL   16384
#define C_CAND    32
#define THREADS   256
#define NBLOCKS   ((B_TOTAL * C_CAND / 4) / THREADS)   // 512

__device__ float        g_partials[NBLOCKS];
__device__ unsigned int g_count = 0;

__global__ __launch_bounds__(THREADS)
void sym_loss_fused(const float* __restrict__ pred,   // (B, C, 3, 3)
                    const float* __restrict__ gt,     // (B, 3, 3)
                    float* __restrict__ out)
{
    __shared__ float swarp[THREADS / 32];
    __shared__ bool  sIsLast;

    const int tid = threadIdx.x;
    const int q   = blockIdx.x * THREADS + tid;   // quad id: 4 candidates
    const int b   = q >> 3;                       // batch (8 quads per batch)

    // 9 contiguous, 16B-aligned float4 per thread; consecutive lanes cover
    // consecutive 144B chunks -> warp spans 4608B fully-used contiguous.
    const float4* __restrict__ src = reinterpret_cast<const float4*>(pred) + (size_t)q * 9;
    float4 v[9];
    #pragma unroll
    for (int i = 0; i < 9; ++i) v[i] = __ldg(src + i);
    const float* a = reinterpret_cast<const float*>(v);   // 36 floats, 4 matrices

    // gt: 8-lane groups share an address (one bcast); 4 batches/warp = 2 lines.
    const float* __restrict__ g = gt + (size_t)b * 9;
    float gr[9];
    #pragma unroll
    for (int i = 0; i < 9; ++i) gr[i] = __ldg(g + i);

    const float h = 0.8660254037844386f;   // sin(pi/3)
    float maxtr = -4.0f;

    #pragma unroll
    for (int j = 0; j < 4; ++j) {
        const float p0 = a[9*j+0], p1 = a[9*j+1], p2 = a[9*j+2];
        const float p3 = a[9*j+3], p4 = a[9*j+4], p5 = a[9*j+5];
        const float p6 = a[9*j+6], p7 = a[9*j+7], p8 = a[9*j+8];

        // Needed entries of P = R_pred * R_gt^T
        const float P00 = fmaf(p0, gr[0], fmaf(p1, gr[1], p2 * gr[2]));
        const float P01 = fmaf(p0, gr[3], fmaf(p1, gr[4], p2 * gr[5]));
        const float P10 = fmaf(p3, gr[0], fmaf(p4, gr[1], p5 * gr[2]));
        const float P11 = fmaf(p3, gr[3], fmaf(p4, gr[4], p5 * gr[5]));
        const float P22 = fmaf(p6, gr[6], fmaf(p7, gr[7], p8 * gr[8]));

        const float A  = P00 + P11;
        const float Bv = P10 - P01;
        const float D  = P00 - P11;
        const float E  = P01 + P10;

        // max trace over 6 z-rotations (+/- pairs) and 6 two-fold axes
        const float mz = fmaxf(fabsf(A),
                         fmaxf(fabsf(fmaf(h, Bv,  0.5f * A)),
                               fabsf(fmaf(h, Bv, -0.5f * A))));
        const float m2 = fmaxf(fabsf(D),
                         fmaxf(fabsf(fmaf(h, E,  0.5f * D)),
                               fabsf(fmaf(h, E, -0.5f * D))));

        maxtr = fmaxf(maxtr, fmaxf(mz + P22, m2 - P22));
    }

    // max over the 8 lanes owning this batch (xor-closed subgroups)
    #pragma unroll
    for (int off = 1; off < 8; off <<= 1)
        maxtr = fmaxf(maxtr, __shfl_xor_sync(0xFFFFFFFFu, maxtr, off));

    // theta per lane (all 8 lanes of a group hold the same value; SIMT-free)
    float cosv = (maxtr - 1.0f) * 0.5f;
    cosv = fminf(fmaxf(cosv, -1.0f + 1e-7f), 1.0f - 1e-7f);
    float theta = acosf(cosv);

    // Sum over the warp's 4 batch-groups: xor offsets 8,16 visit each 8-lane
    // group exactly once ({l, l^8, l^16, l^24} spans the 4 groups), so the
    // result is g0+g1+g2+g3 with no overcount -> no rescale.
    #pragma unroll
    for (int off = 8; off < 32; off <<= 1)
        theta += __shfl_xor_sync(0xFFFFFFFFu, theta, off);

    if (tid % 32 == 0) swarp[tid >> 5] = theta;
    __syncthreads();

    if (tid == 0) {
        float s = 0.0f;
        #pragma unroll
        for (int i = 0; i < THREADS / 32; ++i) s += swarp[i];
        g_partials[blockIdx.x] = s;
        __threadfence();
        unsigned int old = atomicAdd(&g_count, 1u);
        sIsLast = (old == (unsigned int)(NBLOCKS - 1));
    }
    __syncthreads();

    if (sIsLast) {
        __threadfence();   // acquire: see all blocks' partials
        float s = g_partials[tid] + g_partials[tid + THREADS];   // 512 partials
        #pragma unroll
        for (int off = 16; off > 0; off >>= 1)
            s += __shfl_xor_sync(0xFFFFFFFFu, s, off);
        if ((tid & 31) == 0) swarp[tid >> 5] = s;
        __syncthreads();
        if (tid == 0) {
            float t = 0.0f;
            #pragma unroll
            for (int i = 0; i < THREADS / 32; ++i) t += swarp[i];
            out[0] = t / (float)B_TOTAL;
            g_count = 0;                        // reset for next graph replay
        }
    }
}

extern "C" void kernel_launch(void* const* d_in, const int* in_sizes, int n_in,
                              void* d_out, int out_size)
{
    const float* pred = (const float*)d_in[0];   // (B, C, 3, 3)
    const float* gt   = (const float*)d_in[1];   // (B, 3, 3)
    // d_in[2] = rot_mats: P622 rotations, folded into closed-form constants.
    float* out = (float*)d_out;

    sym_loss_fused<<<NBLOCKS, THREADS>>>(pred, gt, out);
}

// round 7
// speedup vs baseline: 1.1512x; 1.1512x over previous
#include <cuda_runtime.h>
#include <cuda_bf16.h>
#include <cstdint>

// SymmetryAwareLossLoop: mean over B of min over (C,S) geodesic angle.
// tr(R_pred (R_s R_gt)^T) = <R_s, P>, P = R_pred R_gt^T; P622 traces collapse
// to closed form (+/- pairs); acos monotone -> one acosf per batch group.
//
// R7: register pressure (regs=43) was serializing the 9 LDG.128 per thread
// (MLP_eff ~3 -> 2TB/s latency-bound). Replace per-thread loads with ONE
// cp.async.bulk per CTA (36KB pred slab + 1.1KB gt slab) completing on an
// mbarrier: full-slab memory concurrency with zero register cost. Compute
// reads smem (LDS.128). Fused fence+counter final reduction.

#define B_TOTAL   16384
#define C_CAND    32
#define THREADS   256
#define BATCH_PB  32                     // batches per CTA (8 quads/batch)
#define NBLOCKS   (B_TOTAL / BATCH_PB)   // 512
#define PRED_BYTES (BATCH_PB * C_CAND * 9 * 4)   // 36864
#define GT_BYTES   (BATCH_PB * 9 * 4)            // 1152

__device__ float        g_partials[NBLOCKS];
__device__ unsigned int g_count = 0;

__global__ __launch_bounds__(THREADS)
void sym_loss_fused(const float* __restrict__ pred,   // (B, C, 3, 3)
                    const float* __restrict__ gt,     // (B, 3, 3)
                    float* __restrict__ out)
{
    __shared__ alignas(16) unsigned char s_pred[PRED_BYTES];
    __shared__ alignas(16) unsigned char s_gt[GT_BYTES];
    __shared__ alignas(8)  unsigned long long s_mbar;
    __shared__ float swarp[THREADS / 32];
    __shared__ bool  sIsLast;

    const int tid = threadIdx.x;

    const uint32_t mb = (uint32_t)__cvta_generic_to_shared(&s_mbar);
    if (tid == 0) {
        asm volatile("mbarrier.init.shared.b64 [%0], %1;" :: "r"(mb), "r"(1u) : "memory");
    }
    __syncthreads();   // mbarrier visible to all before anyone waits

    if (tid == 0) {
        asm volatile("mbarrier.arrive.expect_tx.shared.b64 _, [%0], %1;"
                     :: "r"(mb), "r"((uint32_t)(PRED_BYTES + GT_BYTES)) : "memory");
        const uint32_t dp = (uint32_t)__cvta_generic_to_shared(s_pred);
        const uint32_t dg = (uint32_t)__cvta_generic_to_shared(s_gt);
        const float* srcp = pred + (size_t)blockIdx.x * (PRED_BYTES / 4);
        const float* srcg = gt   + (size_t)blockIdx.x * (GT_BYTES / 4);
        asm volatile("cp.async.bulk.shared::cta.global.mbarrier::complete_tx::bytes [%0], [%1], %2, [%3];"
                     :: "r"(dp), "l"(srcp), "r"((uint32_t)PRED_BYTES), "r"(mb) : "memory");
        asm volatile("cp.async.bulk.shared::cta.global.mbarrier::complete_tx::bytes [%0], [%1], %2, [%3];"
                     :: "r"(dg), "l"(srcg), "r"((uint32_t)GT_BYTES), "r"(mb) : "memory");
    }

    // Wait phase 0 completion (fresh mbarrier each launch -> parity 0).
    {
        asm volatile(
            "{\n\t"
            ".reg .pred P;\n\t"
            "WAIT_%=:\n\t"
            "mbarrier.try_wait.parity.shared.b64 P, [%0], %1;\n\t"
            "@P bra DONE_%=;\n\t"
            "bra WAIT_%=;\n\t"
            "DONE_%=:\n\t"
            "}"
            :: "r"(mb), "r"(0u) : "memory");
    }

    // thread = quad of 4 candidates; 8 quads per batch.
    const int lb = tid >> 3;                       // local batch 0..31

    const float4* __restrict__ sp = reinterpret_cast<const float4*>(s_pred + tid * 144);
    float4 v[9];
    #pragma unroll
    for (int i = 0; i < 9; ++i) v[i] = sp[i];      // LDS.128 (4-way conflicts, cheap)
    const float* a = reinterpret_cast<const float*>(v);   // 36 floats, 4 matrices

    const float* __restrict__ gp = reinterpret_cast<const float*>(s_gt + lb * 36);
    float gr[9];
    #pragma unroll
    for (int i = 0; i < 9; ++i) gr[i] = gp[i];

    const float h = 0.8660254037844386f;   // sin(pi/3)
    float maxtr = -4.0f;

    #pragma unroll
    for (int j = 0; j < 4; ++j) {
        const float p0 = a[9*j+0], p1 = a[9*j+1], p2 = a[9*j+2];
        const float p3 = a[9*j+3], p4 = a[9*j+4], p5 = a[9*j+5];
        const float p6 = a[9*j+6], p7 = a[9*j+7], p8 = a[9*j+8];

        // Needed entries of P = R_pred * R_gt^T
        const float P00 = fmaf(p0, gr[0], fmaf(p1, gr[1], p2 * gr[2]));
        const float P01 = fmaf(p0, gr[3], fmaf(p1, gr[4], p2 * gr[5]));
        const float P10 = fmaf(p3, gr[0], fmaf(p4, gr[1], p5 * gr[2]));
        const float P11 = fmaf(p3, gr[3], fmaf(p4, gr[4], p5 * gr[5]));
        const float P22 = fmaf(p6, gr[6], fmaf(p7, gr[7], p8 * gr[8]));

        const float A  = P00 + P11;
        const float Bv = P10 - P01;
        const float D  = P00 - P11;
        const float E  = P01 + P10;

        const float mz = fmaxf(fabsf(A),
                         fmaxf(fabsf(fmaf(h, Bv,  0.5f * A)),
                               fabsf(fmaf(h, Bv, -0.5f * A))));
        const float m2 = fmaxf(fabsf(D),
                         fmaxf(fabsf(fmaf(h, E,  0.5f * D)),
                               fabsf(fmaf(h, E, -0.5f * D))));

        maxtr = fmaxf(maxtr, fmaxf(mz + P22, m2 - P22));
    }

    // max over the 8 lanes owning this batch (xor-closed subgroups)
    #pragma unroll
    for (int off = 1; off < 8; off <<= 1)
        maxtr = fmaxf(maxtr, __shfl_xor_sync(0xFFFFFFFFu, maxtr, off));

    float cosv = (maxtr - 1.0f) * 0.5f;
    cosv = fminf(fmaxf(cosv, -1.0f + 1e-7f), 1.0f - 1e-7f);
    float theta = acosf(cosv);

    // xor offsets 8,16 visit each 8-lane group exactly once -> sum of the
    // warp's 4 batch thetas, no overcount.
    #pragma unroll
    for (int off = 8; off < 32; off <<= 1)
        theta += __shfl_xor_sync(0xFFFFFFFFu, theta, off);

    if ((tid & 31) == 0) swarp[tid >> 5] = theta;
    __syncthreads();

    if (tid == 0) {
        float s = 0.0f;
        #pragma unroll
        for (int i = 0; i < THREADS / 32; ++i) s += swarp[i];
        g_partials[blockIdx.x] = s;
        __threadfence();
        unsigned int old = atomicAdd(&g_count, 1u);
        sIsLast = (old == (unsigned int)(NBLOCKS - 1));
    }
    __syncthreads();

    if (sIsLast) {
        __threadfence();   // acquire: see all blocks' partials
        float s = g_partials[tid] + g_partials[tid + THREADS];   // 512 partials
        #pragma unroll
        for (int off = 16; off > 0; off >>= 1)
            s += __shfl_xor_sync(0xFFFFFFFFu, s, off);
        if ((tid & 31) == 0) swarp[tid >> 5] = s;
        __syncthreads();
        if (tid == 0) {
            float t = 0.0f;
            #pragma unroll
            for (int i = 0; i < THREADS / 32; ++i) t += swarp[i];
            out[0] = t / (float)B_TOTAL;
            g_count = 0;                        // reset for next graph replay
        }
    }
}

extern "C" void kernel_launch(void* const* d_in, const int* in_sizes, int n_in,
                              void* d_out, int out_size)
{
    const float* pred = (const float*)d_in[0];   // (B, C, 3, 3)
    const float* gt   = (const float*)d_in[1];   // (B, 3, 3)
    // d_in[2] = rot_mats: P622 rotations, folded into closed-form constants.
    float* out = (float*)d_out;

    sym_loss_fused<<<NBLOCKS, THREADS>>>(pred, gt, out);
}

// round 9
// speedup vs baseline: 1.2316x; 1.0699x over previous
#include <cuda_runtime.h>
#include <cuda_bf16.h>
#include <cstdint>

// SymmetryAwareLossLoop: mean over B of min over (C,S) geodesic angle.
// tr(R_pred (R_s R_gt)^T) = <R_s, P>, P = R_pred R_gt^T; P622 traces collapse
// to closed form (+/- pairs); acos monotone -> one acosf per batch group.
//
// R8: the kernel is a one-wave burst -> latency chain, not BW, dominates
// (R2/R6/R7 all ~2TB/s with nothing saturated). Compress the chain:
//  - 256 CTAs (launch ramp + partials halved), 64 batches each
//  - 2-chunk TMA pipeline (both bulk copies issued at t=0; compute chunk 0
//    while chunk 1 streams -> compute fully hidden)
//  - dynamic smem (74KB/CTA, 3 CTAs/SM, single wave)

#define B_TOTAL   16384
#define C_CAND    32
#define THREADS   256
#define NBLOCKS   256
#define BATCH_PC  32                                  // batches per chunk
#define CHUNK_BYTES (BATCH_PC * C_CAND * 9 * 4)       // 36864
#define GT_BYTES    (2 * BATCH_PC * 9 * 4)            // 2304 (64 batches)
#define SMEM_DYN    (2 * CHUNK_BYTES + GT_BYTES)      // 76032

__device__ float        g_partials[NBLOCKS];
__device__ unsigned int g_count = 0;

extern __shared__ unsigned char s_dyn[];

__global__ __launch_bounds__(THREADS)
void sym_loss_fused(const float* __restrict__ pred,   // (B, C, 3, 3)
                    const float* __restrict__ gt,     // (B, 3, 3)
                    float* __restrict__ out)
{
    __shared__ alignas(8) unsigned long long s_mbar[2];
    __shared__ float swarp[THREADS / 32];
    __shared__ bool  sIsLast;

    const int tid = threadIdx.x;
    const int cb  = blockIdx.x;

    const uint32_t mb0 = (uint32_t)__cvta_generic_to_shared(&s_mbar[0]);
    const uint32_t mb1 = (uint32_t)__cvta_generic_to_shared(&s_mbar[1]);

    if (tid == 0) {
        asm volatile("mbarrier.init.shared.b64 [%0], %1;" :: "r"(mb0), "r"(1u) : "memory");
        asm volatile("mbarrier.init.shared.b64 [%0], %1;" :: "r"(mb1), "r"(1u) : "memory");
    }
    __syncthreads();   // mbarriers visible before anyone waits

    if (tid == 0) {
        const uint32_t dp = (uint32_t)__cvta_generic_to_shared(s_dyn);
        const uint32_t dg = dp + 2 * CHUNK_BYTES;
        const float* srcp = pred + (size_t)cb * 2 * (CHUNK_BYTES / 4);
        const float* srcg = gt   + (size_t)cb * (GT_BYTES / 4);

        // chunk 0 + gt on mbar0; chunk 1 on mbar1. Both in flight immediately.
        asm volatile("mbarrier.arrive.expect_tx.shared.b64 _, [%0], %1;"
                     :: "r"(mb0), "r"((uint32_t)(CHUNK_BYTES + GT_BYTES)) : "memory");
        asm volatile("cp.async.bulk.shared::cta.global.mbarrier::complete_tx::bytes [%0], [%1], %2, [%3];"
                     :: "r"(dp), "l"(srcp), "r"((uint32_t)CHUNK_BYTES), "r"(mb0) : "memory");
        asm volatile("cp.async.bulk.shared::cta.global.mbarrier::complete_tx::bytes [%0], [%1], %2, [%3];"
                     :: "r"(dg), "l"(srcg), "r"((uint32_t)GT_BYTES), "r"(mb0) : "memory");

        asm volatile("mbarrier.arrive.expect_tx.shared.b64 _, [%0], %1;"
                     :: "r"(mb1), "r"((uint32_t)CHUNK_BYTES) : "memory");
        asm volatile("cp.async.bulk.shared::cta.global.mbarrier::complete_tx::bytes [%0], [%1], %2, [%3];"
                     :: "r"(dp + CHUNK_BYTES), "l"(srcp + CHUNK_BYTES / 4),
                        "r"((uint32_t)CHUNK_BYTES), "r"(mb1) : "memory");
    }

    const float h = 0.8660254037844386f;   // sin(pi/3)
    float thetaSum = 0.0f;

    #pragma unroll
    for (int k = 0; k < 2; ++k) {
        const uint32_t mb = k ? mb1 : mb0;
        asm volatile(
            "{\n\t"
            ".reg .pred P;\n\t"
            "WAIT_%=:\n\t"
            "mbarrier.try_wait.parity.shared.b64 P, [%0], %1;\n\t"
            "@P bra DONE_%=;\n\t"
            "bra WAIT_%=;\n\t"
            "DONE_%=:\n\t"
            "}"
            :: "r"(mb), "r"(0u) : "memory");

        // thread = quad of 4 candidates; chunk = 32 batches = 256 quads.
        const float4* __restrict__ sp =
            reinterpret_cast<const float4*>(s_dyn + k * CHUNK_BYTES + tid * 144);
        float4 v[9];
        #pragma unroll
        for (int i = 0; i < 9; ++i) v[i] = sp[i];
        const float* a = reinterpret_cast<const float*>(v);

        const float* __restrict__ gp = reinterpret_cast<const float*>(
            s_dyn + 2 * CHUNK_BYTES + (k * BATCH_PC + (tid >> 3)) * 36);
        float gr[9];
        #pragma unroll
        for (int i = 0; i < 9; ++i) gr[i] = gp[i];

        float maxtr = -4.0f;
        #pragma unroll
        for (int j = 0; j < 4; ++j) {
            const float p0 = a[9*j+0], p1 = a[9*j+1], p2 = a[9*j+2];
            const float p3 = a[9*j+3], p4 = a[9*j+4], p5 = a[9*j+5];
            const float p6 = a[9*j+6], p7 = a[9*j+7], p8 = a[9*j+8];

            const float P00 = fmaf(p0, gr[0], fmaf(p1, gr[1], p2 * gr[2]));
            const float P01 = fmaf(p0, gr[3], fmaf(p1, gr[4], p2 * gr[5]));
            const float P10 = fmaf(p3, gr[0], fmaf(p4, gr[1], p5 * gr[2]));
            const float P11 = fmaf(p3, gr[3], fmaf(p4, gr[4], p5 * gr[5]));
            const float P22 = fmaf(p6, gr[6], fmaf(p7, gr[7], p8 * gr[8]));

            const float A  = P00 + P11;
            const float Bv = P10 - P01;
            const float D  = P00 - P11;
            const float E  = P01 + P10;

            const float mz = fmaxf(fabsf(A),
                             fmaxf(fabsf(fmaf(h, Bv,  0.5f * A)),
                                   fabsf(fmaf(h, Bv, -0.5f * A))));
            const float m2 = fmaxf(fabsf(D),
                             fmaxf(fabsf(fmaf(h, E,  0.5f * D)),
                                   fabsf(fmaf(h, E, -0.5f * D))));

            maxtr = fmaxf(maxtr, fmaxf(mz + P22, m2 - P22));
        }

        // max over the 8 lanes owning this batch (xor-closed subgroups)
        #pragma unroll
        for (int off = 1; off < 8; off <<= 1)
            maxtr = fmaxf(maxtr, __shfl_xor_sync(0xFFFFFFFFu, maxtr, off));

        float cosv = (maxtr - 1.0f) * 0.5f;
        cosv = fminf(fmaxf(cosv, -1.0f + 1e-7f), 1.0f - 1e-7f);
        float theta = acosf(cosv);

        // xor offsets 8,16 hit each 8-lane group exactly once -> sum of the
        // warp's 4 batch thetas, no overcount.
        #pragma unroll
        for (int off = 8; off < 32; off <<= 1)
            theta += __shfl_xor_sync(0xFFFFFFFFu, theta, off);

        thetaSum += theta;
    }

    if ((tid & 31) == 0) swarp[tid >> 5] = thetaSum;
    __syncthreads();

    if (tid == 0) {
        float s = 0.0f;
        #pragma unroll
        for (int i = 0; i < THREADS / 32; ++i) s += swarp[i];
        g_partials[cb] = s;
        __threadfence();
        unsigned int old = atomicAdd(&g_count, 1u);
        sIsLast = (old == (unsigned int)(NBLOCKS - 1));
    }
    __syncthreads();

    if (sIsLast) {
        __threadfence();   // acquire: see all blocks' partials
        float s = g_partials[tid];                  // 256 partials, one each
        #pragma unroll
        for (int off = 16; off > 0; off >>= 1)
            s += __shfl_xor_sync(0xFFFFFFFFu, s, off);
        if ((tid & 31) == 0) swarp[tid >> 5] = s;
        __syncthreads();
        if (tid == 0) {
            float t = 0.0f;
            #pragma unroll
            for (int i = 0; i < THREADS / 32; ++i) t += swarp[i];
            out[0] = t / (float)B_TOTAL;
            g_count = 0;                            // reset for next replay
        }
    }
}

extern "C" void kernel_launch(void* const* d_in, const int* in_sizes, int n_in,
                              void* d_out, int out_size)
{
    const float* pred = (const float*)d_in[0];   // (B, C, 3, 3)
    const float* gt   = (const float*)d_in[1];   // (B, 3, 3)
    // d_in[2] = rot_mats: P622 rotations, folded into closed-form constants.
    float* out = (float*)d_out;

    // Idempotent, not a stream op (not captured); needed for 74KB dynamic smem.
    cudaFuncSetAttribute(sym_loss_fused,
                         cudaFuncAttributeMaxDynamicSharedMemorySize, SMEM_DYN);

    sym_loss_fused<<<NBLOCKS, THREADS, SMEM_DYN>>>(pred, gt, out);
}